// round 2
// baseline (speedup 1.0000x reference)
#include <cuda_runtime.h>

// AttentionFusion: fused = sigmoid((x1-x2)@w) * x1 + (1-sigmoid) * x2
// N = 16384 rows, D = 2048 cols, fp32.
// One CTA per row; 256 threads; each thread handles 2 float4 (8 elems).
// Row payload stays in registers -> x1/x2 read exactly once from DRAM.

#define N_ROWS 16384
#define D_COLS 2048
#define THREADS 256
// float4s per row = 2048/4 = 512; per thread = 512/256 = 2

__global__ __launch_bounds__(THREADS, 8)
void attention_fusion_kernel(const float* __restrict__ x1,
                             const float* __restrict__ x2,
                             const float* __restrict__ w,
                             float* __restrict__ fused,
                             float* __restrict__ alpha) {
    const int row = blockIdx.x;
    const int tid = threadIdx.x;

    const float4* __restrict__ x1r = reinterpret_cast<const float4*>(x1) + (size_t)row * (D_COLS / 4);
    const float4* __restrict__ x2r = reinterpret_cast<const float4*>(x2) + (size_t)row * (D_COLS / 4);
    const float4* __restrict__ w4  = reinterpret_cast<const float4*>(w);

    // Two coalesced float4 loads per stream, strided by blockDim
    float4 a0 = x1r[tid];
    float4 a1 = x1r[tid + THREADS];
    float4 b0 = x2r[tid];
    float4 b1 = x2r[tid + THREADS];
    float4 w0 = w4[tid];
    float4 w1 = w4[tid + THREADS];

    // Partial of d = dot(x1 - x2, w)
    float d = (a0.x - b0.x) * w0.x;
    d = fmaf(a0.y - b0.y, w0.y, d);
    d = fmaf(a0.z - b0.z, w0.z, d);
    d = fmaf(a0.w - b0.w, w0.w, d);
    d = fmaf(a1.x - b1.x, w1.x, d);
    d = fmaf(a1.y - b1.y, w1.y, d);
    d = fmaf(a1.z - b1.z, w1.z, d);
    d = fmaf(a1.w - b1.w, w1.w, d);

    // Warp reduce
    #pragma unroll
    for (int off = 16; off > 0; off >>= 1)
        d += __shfl_xor_sync(0xFFFFFFFFu, d, off);

    __shared__ float warp_sums[THREADS / 32];
    __shared__ float alpha1_sh;
    const int lane = tid & 31;
    const int warp = tid >> 5;
    if (lane == 0) warp_sums[warp] = d;
    __syncthreads();

    if (warp == 0) {
        float v = (lane < THREADS / 32) ? warp_sums[lane] : 0.0f;
        #pragma unroll
        for (int off = 4; off > 0; off >>= 1)
            v += __shfl_xor_sync(0xFFFFFFFFu, v, off);
        if (lane == 0) {
            // sigmoid(v), numerically stable for fp32 range here
            float a = 1.0f / (1.0f + expf(-v));
            alpha1_sh = a;
            alpha[(size_t)row * 2 + 0] = a;
            alpha[(size_t)row * 2 + 1] = 1.0f - a;
        }
    }
    __syncthreads();

    const float al = alpha1_sh;
    const float be = 1.0f - al;

    float4* __restrict__ outr = reinterpret_cast<float4*>(fused) + (size_t)row * (D_COLS / 4);

    float4 o0, o1;
    o0.x = fmaf(al, a0.x - b0.x, b0.x);  // al*a + (1-al)*b = al*(a-b) + b
    o0.y = fmaf(al, a0.y - b0.y, b0.y);
    o0.z = fmaf(al, a0.z - b0.z, b0.z);
    o0.w = fmaf(al, a0.w - b0.w, b0.w);
    o1.x = fmaf(al, a1.x - b1.x, b1.x);
    o1.y = fmaf(al, a1.y - b1.y, b1.y);
    o1.z = fmaf(al, a1.z - b1.z, b1.z);
    o1.w = fmaf(al, a1.w - b1.w, b1.w);
    (void)be;

    outr[tid] = o0;
    outr[tid + THREADS] = o1;
}

extern "C" void kernel_launch(void* const* d_in, const int* in_sizes, int n_in,
                              void* d_out, int out_size) {
    const float* x1 = (const float*)d_in[0];
    const float* x2 = (const float*)d_in[1];
    const float* w  = (const float*)d_in[2];
    float* out = (float*)d_out;

    float* fused = out;                               // [N, D]
    float* alpha = out + (size_t)N_ROWS * D_COLS;     // [N, 2]

    attention_fusion_kernel<<<N_ROWS, THREADS>>>(x1, x2, w, fused, alpha);
}